// round 4
// baseline (speedup 1.0000x reference)
#include <cuda_runtime.h>

#define B 32
#define M 32
#define C 1024
#define R 28
#define INV_R2 (1.0f / (R * R))

#define IMGS_PER_BLK 8
#define ROWS_PER_BLK (IMGS_PER_BLK * R)          // 224
#define F4_PER_BLK (ROWS_PER_BLK * R / 4)        // 1568
#define THREADS 224
#define F4_PER_THREAD (F4_PER_BLK / THREADS)     // 7
#define BLKS_PER_B (C / IMGS_PER_BLK)            // 128

// Scratch (allocation-free rule: __device__ global)
__device__ float g_col[B * M * R];   // column sums of Masks: (B, M, R)

// ---------------------------------------------------------------------------
// Kernel 1: col[b,m,j] = sum_i Masks[b,m,i,j], f4-vectorized.
// Thread per (bm, jf4): jf4 in [0,7). Element (i, j) lives at f4 index
// i*7 + jf4 within the image (row = 28 floats = 7 f4). Sum 28 f4 down the
// i-stride (112B), MLP=28, store one float4 directly into g_col layout.
// ---------------------------------------------------------------------------
__global__ void reduce_M_kernel(const float* __restrict__ Mk) {
    int tid = blockIdx.x * blockDim.x + threadIdx.x;
    if (tid >= B * M * (R / 4)) return;
    int jf4 = tid % (R / 4);
    int bm  = tid / (R / 4);
    const float4* p = reinterpret_cast<const float4*>(Mk) + (size_t)bm * (R * R / 4) + jf4;
    float4 s = make_float4(0.f, 0.f, 0.f, 0.f);
#pragma unroll
    for (int i = 0; i < R; i++) {
        float4 w = p[i * (R / 4)];
        s.x += w.x; s.y += w.y; s.z += w.z; s.w += w.w;
    }
    reinterpret_cast<float4*>(g_col)[tid] = s;
}

// ---------------------------------------------------------------------------
// Kernel 2 (fused): coalesced stream of F -> immediate f4 hsum -> scalar
// partials in smem -> segmented row-sum -> einsum tail.
// __launch_bounds__(224, 7): caps regs at ~40 so the register file admits
// 7 blocks/SM (49 warps, ~73% occ) instead of 5 (35 warps, 48%).
// ---------------------------------------------------------------------------
__global__ void __launch_bounds__(THREADS, 7)
fused_rowsum_einsum_kernel(const float* __restrict__ F, float* __restrict__ out) {
    __shared__ float partial[F4_PER_BLK];     // 1568 floats = 6.3 KB
    __shared__ float rowsum[ROWS_PER_BLK];    // 224 floats: [c_local*28 + i]
    __shared__ float col_s[M * R];            // 896 floats: [m*28 + r]

    const int tid = threadIdx.x;
    const int blk = blockIdx.x;
    const int b   = blk / BLKS_PER_B;

    // Stage col[b] (L2-hot: 128 blocks share it)
    {
        const float* cp = g_col + b * (M * R);
#pragma unroll
        for (int k = 0; k < 4; k++)
            col_s[k * THREADS + tid] = cp[k * THREADS + tid];
    }

    // Coalesced streaming load (warp reads 512B contiguous per LDG.128,
    // all 7 issued back-to-back: MLP=7) + immediate horizontal sum.
    const float4* src = reinterpret_cast<const float4*>(F) + (size_t)blk * F4_PER_BLK;
    float4 v[F4_PER_THREAD];
#pragma unroll
    for (int k = 0; k < F4_PER_THREAD; k++) v[k] = src[k * THREADS + tid];
#pragma unroll
    for (int k = 0; k < F4_PER_THREAD; k++)
        partial[k * THREADS + tid] = (v[k].x + v[k].y) + (v[k].z + v[k].w);
    __syncthreads();

    // Segmented row sum: row t = partial[7t .. 7t+6]; 7 coprime to 32 ->
    // per-phase bank permutation -> conflict-free.
    {
        float s = 0.0f;
#pragma unroll
        for (int k = 0; k < F4_PER_THREAD; k++) s += partial[tid * F4_PER_THREAD + k];
        rowsum[tid] = s;
    }
    __syncthreads();

    // Einsum tail: 256 outputs = 32 m x 8 c_local
    const int c0 = (blk % BLKS_PER_B) * IMGS_PER_BLK;
    for (int o = tid; o < M * IMGS_PER_BLK; o += THREADS) {
        int m  = o / IMGS_PER_BLK;
        int cl = o % IMGS_PER_BLK;
        float acc = 0.0f;
#pragma unroll
        for (int r = 0; r < R; r++)
            acc += col_s[m * R + r] * rowsum[cl * R + r];
        out[((size_t)b * M + m) * C + c0 + cl] = acc * INV_R2;
    }
}

extern "C" void kernel_launch(void* const* d_in, const int* in_sizes, int n_in,
                              void* d_out, int out_size) {
    const float* F  = (const float*)d_in[0];  // (B, C, R, R)
    const float* Mk = (const float*)d_in[1];  // (B, M, R, R)
    float* out = (float*)d_out;               // (B, M, C)

    {
        int n = B * M * (R / 4);  // 7168
        reduce_M_kernel<<<(n + 255) / 256, 256>>>(Mk);
    }
    {
        int nblks = (B * C) / IMGS_PER_BLK;   // 4096
        fused_rowsum_einsum_kernel<<<nblks, THREADS>>>(F, out);
    }
}

// round 5
// speedup vs baseline: 1.0837x; 1.0837x over previous
#include <cuda_runtime.h>

#define B 32
#define M 32
#define C 1024
#define R 28
#define INV_R2 (1.0f / (R * R))

#define IMGS_PER_BLK 8
#define ROWS_PER_BLK (IMGS_PER_BLK * R)          // 224
#define F4_PER_TILE (ROWS_PER_BLK * R / 4)       // 1568
#define THREADS 224
#define F4_PER_THREAD (F4_PER_TILE / THREADS)    // 7
#define TILES_PER_B (C / IMGS_PER_BLK)           // 128
#define TILES_PER_BLK 8
#define NBLKS ((B * C / IMGS_PER_BLK) / TILES_PER_BLK)   // 512

// Scratch (allocation-free rule: __device__ global)
__device__ float g_col[B * M * R];   // column sums of Masks: (B, M, R)

// ---------------------------------------------------------------------------
// Kernel 1: col[b,m,j] = sum_i Masks[b,m,i,j].
// One thread per (b,m,j) = 28672 threads / 112 blocks (wide: ~1 wave over
// 148 SMs, unlike the 28-block f4 version that underutilized the chip).
// 28 independent stride-112B loads per thread (MLP=28), ~coalesced across j.
// ---------------------------------------------------------------------------
__global__ void reduce_M_kernel(const float* __restrict__ Mk) {
    int tid = blockIdx.x * blockDim.x + threadIdx.x;
    if (tid >= B * M * R) return;
    int j  = tid % R;
    int bm = tid / R;
    const float* p = Mk + (size_t)bm * R * R + j;
    float s = 0.0f;
#pragma unroll
    for (int i = 0; i < R; i++) s += p[i * R];
    g_col[tid] = s;
}

// ---------------------------------------------------------------------------
// Kernel 2 (fused + pipelined): each block owns 8 consecutive tiles (64
// channels, all same b -> col_s staged once). Tile t+1's 7 coalesced LDG.128
// are issued BEFORE tile t is consumed, so global loads stay in flight
// through the rowsum/einsum/barrier phases (the DRAM bubbles of R3).
// Double register buffer: ~70 regs -> 3 blocks/SM (21 warps), in-flight
// bytes 21*7*512B = 75KB/SM >> Little's-law need (~12KB).
// ---------------------------------------------------------------------------
__global__ void __launch_bounds__(THREADS, 3)
fused_rowsum_einsum_kernel(const float* __restrict__ F, float* __restrict__ out) {
    __shared__ float partial[F4_PER_TILE];    // 1568 floats = 6.3 KB
    __shared__ float rowsum[ROWS_PER_BLK];    // 224 floats: [c_local*28 + i]
    __shared__ float col_s[M * R];            // 896 floats: [m*28 + r]

    const int tid   = threadIdx.x;
    const int tile0 = blockIdx.x * TILES_PER_BLK;
    const int b     = tile0 / TILES_PER_B;    // all 8 tiles share b (8 | 128)

    // Stage col[b] once per block (L2-hot: 16 blocks share it)
    {
        const float* cp = g_col + b * (M * R);
#pragma unroll
        for (int k = 0; k < 4; k++)
            col_s[k * THREADS + tid] = cp[k * THREADS + tid];
    }

    const float4* src = reinterpret_cast<const float4*>(F) + (size_t)tile0 * F4_PER_TILE;

    // Prologue: loads for tile 0
    float4 cur[F4_PER_THREAD], nxt[F4_PER_THREAD];
#pragma unroll
    for (int k = 0; k < F4_PER_THREAD; k++) cur[k] = src[k * THREADS + tid];

#pragma unroll 1
    for (int t = 0; t < TILES_PER_BLK; t++) {
        // Prefetch tile t+1 while tile t is still unconsumed
        if (t + 1 < TILES_PER_BLK) {
            const float4* nsrc = src + (size_t)(t + 1) * F4_PER_TILE;
#pragma unroll
            for (int k = 0; k < F4_PER_THREAD; k++) nxt[k] = nsrc[k * THREADS + tid];
        }

        // f4 horizontal sums -> scalar partials (stride-1 STS: conflict-free)
#pragma unroll
        for (int k = 0; k < F4_PER_THREAD; k++)
            partial[k * THREADS + tid] = (cur[k].x + cur[k].y) + (cur[k].z + cur[k].w);
        __syncthreads();

        // Segmented row sum: row tid = partial[7*tid .. 7*tid+6]
        // (7 coprime to 32 -> per-phase bank permutation -> conflict-free)
        {
            float s = 0.0f;
#pragma unroll
            for (int k = 0; k < F4_PER_THREAD; k++)
                s += partial[tid * F4_PER_THREAD + k];
            rowsum[tid] = s;
        }
        __syncthreads();

        // Einsum tail for this tile: 256 outputs = 32 m x 8 c_local
        const int c0 = ((tile0 + t) % TILES_PER_B) * IMGS_PER_BLK;
        for (int o = tid; o < M * IMGS_PER_BLK; o += THREADS) {
            int m  = o / IMGS_PER_BLK;
            int cl = o % IMGS_PER_BLK;
            float acc = 0.0f;
#pragma unroll
            for (int r = 0; r < R; r++)
                acc += col_s[m * R + r] * rowsum[cl * R + r];
            out[((size_t)b * M + m) * C + c0 + cl] = acc * INV_R2;
        }
        // NOTE: no extra sync needed here — next iteration writes `partial`
        // (einsum reads only rowsum/col_s), and the sync after the partial
        // writes separates this iteration's rowsum reads from the next
        // rowsum write.

#pragma unroll
        for (int k = 0; k < F4_PER_THREAD; k++) cur[k] = nxt[k];
    }
}

extern "C" void kernel_launch(void* const* d_in, const int* in_sizes, int n_in,
                              void* d_out, int out_size) {
    const float* F  = (const float*)d_in[0];  // (B, C, R, R)
    const float* Mk = (const float*)d_in[1];  // (B, M, R, R)
    float* out = (float*)d_out;               // (B, M, C)

    {
        int n = B * M * R;  // 28672
        reduce_M_kernel<<<(n + 255) / 256, 256>>>(Mk);
    }
    fused_rowsum_einsum_kernel<<<NBLKS, THREADS>>>(F, out);
}

// round 6
// speedup vs baseline: 1.2567x; 1.1596x over previous
#include <cuda_runtime.h>

#define B 32
#define M 32
#define C 1024
#define R 28
#define INV_R2 (1.0f / (R * R))

#define IMGS_PER_BLK 8
#define ROWS_PER_BLK (IMGS_PER_BLK * R)          // 224
#define F4_PER_BLK (ROWS_PER_BLK * R / 4)        // 1568
#define THREADS 224
#define F4_PER_THREAD (F4_PER_BLK / THREADS)     // 7
#define BLKS_PER_B (C / IMGS_PER_BLK)            // 128

// Scratch (allocation-free rule: __device__ global)
__device__ float g_col[B * M * R];   // column sums of Masks: (B, M, R)

// ---------------------------------------------------------------------------
// Kernel 1: col[b,m,j] = sum_i Masks[b,m,i,j].
// One thread per (b,m,j) = 28672 threads / 112 blocks (one wide wave).
// 28 independent stride-112B loads per thread (MLP=28), coalesced across j.
// ---------------------------------------------------------------------------
__global__ void reduce_M_kernel(const float* __restrict__ Mk) {
    int tid = blockIdx.x * blockDim.x + threadIdx.x;
    if (tid >= B * M * R) return;
    int j  = tid % R;
    int bm = tid / R;
    const float* p = Mk + (size_t)bm * R * R + j;
    float s = 0.0f;
#pragma unroll
    for (int i = 0; i < R; i++) s += __ldcs(p + i * R);
    g_col[tid] = s;
}

// ---------------------------------------------------------------------------
// Kernel 2 (fused, R3 core): coalesced stream of F (__ldcs: zero reuse,
// evict-first) -> immediate f4 hsum -> scalar partials through smem
// (6.3 KB only) -> segmented row-sum -> einsum tail.
//
// __launch_bounds__(224, 6): reg cap 48 (natural usage is 49) -> keeps the
// 28-reg load batch (MLP=7) intact while admitting 6 blocks/SM (42 warps,
// ~65% occ) instead of 5. R4 showed cap=32 destroys MLP; 48 should not.
// ---------------------------------------------------------------------------
__global__ void __launch_bounds__(THREADS, 6)
fused_rowsum_einsum_kernel(const float* __restrict__ F, float* __restrict__ out) {
    __shared__ float partial[F4_PER_BLK];     // 1568 floats = 6.3 KB
    __shared__ float rowsum[ROWS_PER_BLK];    // 224 floats: [c_local*28 + i]
    __shared__ float col_s[M * R];            // 896 floats: [m*28 + r]

    const int tid = threadIdx.x;
    const int blk = blockIdx.x;
    const int b   = blk / BLKS_PER_B;

    // Stage col[b] (L2-hot: 128 blocks share it)
    {
        const float* cp = g_col + b * (M * R);
#pragma unroll
        for (int k = 0; k < 4; k++)
            col_s[k * THREADS + tid] = cp[k * THREADS + tid];
    }

    // Coalesced streaming load (warp reads 512B contiguous per LDG.128,
    // 7 issued back-to-back: MLP=7) + immediate horizontal sum.
    const float4* src = reinterpret_cast<const float4*>(F) + (size_t)blk * F4_PER_BLK;
    float4 v[F4_PER_THREAD];
#pragma unroll
    for (int k = 0; k < F4_PER_THREAD; k++) v[k] = __ldcs(src + k * THREADS + tid);
#pragma unroll
    for (int k = 0; k < F4_PER_THREAD; k++)
        partial[k * THREADS + tid] = (v[k].x + v[k].y) + (v[k].z + v[k].w);
    __syncthreads();

    // Segmented row sum: row t = partial[7t .. 7t+6]; 7 coprime to 32 ->
    // per-phase bank permutation -> conflict-free.
    {
        float s = 0.0f;
#pragma unroll
        for (int k = 0; k < F4_PER_THREAD; k++) s += partial[tid * F4_PER_THREAD + k];
        rowsum[tid] = s;
    }
    __syncthreads();

    // Einsum tail: 256 outputs = 32 m x 8 c_local
    const int c0 = (blk % BLKS_PER_B) * IMGS_PER_BLK;
    for (int o = tid; o < M * IMGS_PER_BLK; o += THREADS) {
        int m  = o / IMGS_PER_BLK;
        int cl = o % IMGS_PER_BLK;
        float acc = 0.0f;
#pragma unroll
        for (int r = 0; r < R; r++)
            acc += col_s[m * R + r] * rowsum[cl * R + r];
        out[((size_t)b * M + m) * C + c0 + cl] = acc * INV_R2;
    }
}

extern "C" void kernel_launch(void* const* d_in, const int* in_sizes, int n_in,
                              void* d_out, int out_size) {
    const float* F  = (const float*)d_in[0];  // (B, C, R, R)
    const float* Mk = (const float*)d_in[1];  // (B, M, R, R)
    float* out = (float*)d_out;               // (B, M, C)

    {
        int n = B * M * R;  // 28672
        reduce_M_kernel<<<(n + 255) / 256, 256>>>(Mk);
    }
    {
        int nblks = (B * C) / IMGS_PER_BLK;   // 4096
        fused_rowsum_einsum_kernel<<<nblks, THREADS>>>(F, out);
    }
}